// round 8
// baseline (speedup 1.0000x reference)
#include <cuda_runtime.h>
#include <cuda_bf16.h>
#include <cstdint>

#define NFIELD 39
#define VOCAB  200000
#define BATCH  16384
#define ROWSPB 128
#define THREADS 512
#define NCHUNK 10          // 10 chunks x 4 fields (kstep16) = 640 padded k

// B fragments packed for LDS.128: [hl2][kstep40][tpair4][lane32][4xu32]
__device__ __align__(16) uint32_t BfragG[2 * 40 * 4 * 32 * 4];

__global__ void prep_kernel(const float* __restrict__ W1, const float* __restrict__ Wi) {
    int i = blockIdx.x * blockDim.x + threadIdx.x;
    if (i >= 2 * 40 * 4 * 32 * 4) return;
    int reg = i & 3;
    int l   = (i >> 2) & 31;
    int tp  = (i >> 7) & 3;
    int s   = (i >> 9) % 40;
    int hl  = (i >> 9) / 40;
    int t  = tp * 2 + (reg >> 1);
    int n  = t * 8 + (l >> 2);
    int k0 = s * 16 + (l & 3) * 2 + (reg & 1) * 8;
    float v0 = 0.f, v1 = 0.f;
    if (k0 < 624)     v0 = (n < 32) ? W1[n * 624 + k0]     : Wi[(n - 32) * 624 + k0];
    if (k0 + 1 < 624) v1 = (n < 32) ? W1[n * 624 + k0 + 1] : Wi[(n - 32) * 624 + k0 + 1];
    float h0 = __bfloat162float(__float2bfloat16(v0));
    float h1 = __bfloat162float(__float2bfloat16(v1));
    uint32_t w;
    if (hl == 0) {
        asm("cvt.rn.bf16x2.f32 %0, %1, %2;" : "=r"(w) : "f"(h1), "f"(h0));
    } else {
        float r0 = v0 - h0, r1 = v1 - h1;
        asm("cvt.rn.bf16x2.f32 %0, %1, %2;" : "=r"(w) : "f"(r1), "f"(r0));
    }
    BfragG[i] = w;
}

__device__ __forceinline__ uint32_t packbf(float lo_elem, float hi_elem) {
    uint32_t r;
    asm("cvt.rn.bf16x2.f32 %0, %1, %2;" : "=r"(r) : "f"(hi_elem), "f"(lo_elem));
    return r;
}
__device__ __forceinline__ void mma16816(float* d, uint32_t a0, uint32_t a1, uint32_t a2, uint32_t a3,
                                         uint32_t b0, uint32_t b1) {
    asm volatile("mma.sync.aligned.m16n8k16.row.col.f32.bf16.bf16.f32 "
                 "{%0,%1,%2,%3}, {%4,%5,%6,%7}, {%8,%9}, {%0,%1,%2,%3};"
                 : "+f"(d[0]), "+f"(d[1]), "+f"(d[2]), "+f"(d[3])
                 : "r"(a0), "r"(a1), "r"(a2), "r"(a3), "r"(b0), "r"(b1));
}
__device__ __forceinline__ void ldsm4(uint32_t& r0, uint32_t& r1, uint32_t& r2, uint32_t& r3,
                                      uint32_t addr) {
    asm volatile("ldmatrix.sync.aligned.m8n8.x4.shared.b16 {%0,%1,%2,%3}, [%4];"
                 : "=r"(r0), "=r"(r1), "=r"(r2), "=r"(r3) : "r"(addr));
}

// smem layout (bytes):
//   A: 2 bufs x [hl2][slab8][ks4][512B] = 2 x 32768 @ 0
//   B: [hl2][gs40][tp4][lane32][16B] = 163840 @ 65536  (streamed 16KB/chunk)
#define OFF_A 0
#define ABUF  32768
#define OFF_B 65536
#define SMEM_BYTES (65536 + 163840)
// epilogue aliases inside the A region (65536 B):
#define EXP_FO 0
#define EXP_S  16896
#define EXP_M  33792
#define EXP_H  42384

__global__ __launch_bounds__(THREADS, 1)
void pnn_kernel(const int*   __restrict__ Xi,
                const float* __restrict__ Xv,
                const float* __restrict__ tables,
                const float* __restrict__ lin1_w,
                const float* __restrict__ lin1_b,
                const float* __restrict__ lin2_w,
                const float* __restrict__ lin2_b,
                const float* __restrict__ last_w,
                const float* __restrict__ last_b,
                float*       __restrict__ out) {
    extern __shared__ unsigned char smem[];
    const uint32_t sbase = (uint32_t)__cvta_generic_to_shared(smem);

    const int tid = threadIdx.x;
    const int wid = tid >> 5;
    const int l   = tid & 31;
    const int b0  = blockIdx.x * ROWSPB;

    // MMA mapping: warp = (slab, k-half); 48 MMAs/chunk/warp, own partial accs
    const int slab = wid >> 1;       // rows [slab*16, slab*16+16)
    const int kh   = wid & 1;        // ksteps {2kh, 2kh+1} of each chunk

    // gather mapping: 4 items/thread/chunk
    const int qrow  = tid >> 3;      // 0..63
    const int jhalf = (tid >> 2) & 1;
    const int q     = tid & 3;       // 16B segment of the 64B embedding row

    int    nidx[3][4];
    float  nxv[3][4];
    float4 tdat[2][4];
    uint4  tb0, tb1;

    float acc[8][4];
    #pragma unroll
    for (int t = 0; t < 8; ++t)
        #pragma unroll
        for (int r = 0; r < 4; ++r) acc[t][r] = 0.f;

    const uint4* srcB = (const uint4*)BfragG;
    uint4* dstB = (uint4*)(smem + OFF_B);

    auto load_idx = [&](int c, int slot) {
        #pragma unroll
        for (int it = 0; it < 4; ++it) {
            int row = (it >> 1) * 64 + qrow;
            int f = c * 4 + jhalf * 2 + (it & 1);
            if (f < NFIELD) {
                nidx[slot][it] = Xi[(size_t)(b0 + row) * NFIELD + f];
                nxv[slot][it]  = Xv[(size_t)(b0 + row) * NFIELD + f];
            } else {
                nidx[slot][it] = 0;
                nxv[slot][it]  = 0.f;
            }
        }
    };
    auto table_ldg = [&](int c) {
        const int islot = c % 3, tslot = c & 1;
        #pragma unroll
        for (int it = 0; it < 4; ++it) {
            int f = c * 4 + jhalf * 2 + (it & 1);
            if (f < NFIELD)
                tdat[tslot][it] = *(((const float4*)tables) + ((long)f * VOCAB + nidx[islot][it]) * 4 + q);
            else
                tdat[tslot][it] = make_float4(0.f, 0.f, 0.f, 0.f);
        }
    };
    auto cv_store = [&](int c) {
        const int islot = c % 3, tslot = c & 1;
        #pragma unroll
        for (int it = 0; it < 4; ++it) {
            int row = (it >> 1) * 64 + qrow;
            int j = jhalf * 2 + (it & 1);
            float xv = nxv[islot][it];
            float4 t4 = tdat[tslot][it];
            float v0 = t4.x * xv, v1 = t4.y * xv, v2 = t4.z * xv, v3 = t4.w * xv;
            float r0 = v0 - __bfloat162float(__float2bfloat16(v0));
            float r1 = v1 - __bfloat162float(__float2bfloat16(v1));
            float r2 = v2 - __bfloat162float(__float2bfloat16(v2));
            float r3 = v3 - __bfloat162float(__float2bfloat16(v3));
            int sl = row >> 4;
            int inoff = (q >> 1) * 256 + (row & 15) * 16 + (q & 1) * 8;
            unsigned char* bh = smem + (c & 1) * ABUF + ((0 * 8 + sl) * 4 + j) * 512 + inoff;
            unsigned char* bl = smem + (c & 1) * ABUF + ((1 * 8 + sl) * 4 + j) * 512 + inoff;
            *(uint2*)bh = make_uint2(packbf(v0, v1), packbf(v2, v3));
            *(uint2*)bl = make_uint2(packbf(r0, r1), packbf(r2, r3));
        }
    };
    auto bstage_ldg = [&](int c) {
        tb0 = srcB[c * 512 + tid];
        tb1 = srcB[5120 + c * 512 + tid];
    };
    auto bstage_sts = [&](int c) {
        dstB[c * 512 + tid] = tb0;
        dstB[5120 + c * 512 + tid] = tb1;
    };
    auto do_mma = [&](int c) {
        #pragma unroll
        for (int si = 0; si < 2; ++si) {
            const int s = kh * 2 + si;
            const int gs = c * 4 + s;
            uint32_t ah0, ah1, ah2, ah3, al0, al1, al2, al3;
            uint32_t laddr = (uint32_t)((l & 15) * 16 + (l >> 4) * 256);
            ldsm4(ah0, ah1, ah2, ah3,
                  sbase + (c & 1) * ABUF + ((0 * 8 + slab) * 4 + s) * 512 + laddr);
            ldsm4(al0, al1, al2, al3,
                  sbase + (c & 1) * ABUF + ((1 * 8 + slab) * 4 + s) * 512 + laddr);
            #pragma unroll
            for (int tp = 0; tp < 4; ++tp) {
                uint4 Bh = *(const uint4*)(smem + OFF_B + (((0 * 40 + gs) * 4 + tp) * 32 + l) * 16);
                uint4 Bl = *(const uint4*)(smem + OFF_B + (((1 * 40 + gs) * 4 + tp) * 32 + l) * 16);
                mma16816(acc[2 * tp],     ah0, ah1, ah2, ah3, Bh.x, Bh.y);
                mma16816(acc[2 * tp + 1], ah0, ah1, ah2, ah3, Bh.z, Bh.w);
                mma16816(acc[2 * tp],     ah0, ah1, ah2, ah3, Bl.x, Bl.y);
                mma16816(acc[2 * tp + 1], ah0, ah1, ah2, ah3, Bl.z, Bl.w);
                mma16816(acc[2 * tp],     al0, al1, al2, al3, Bh.x, Bh.y);
                mma16816(acc[2 * tp + 1], al0, al1, al2, al3, Bh.z, Bh.w);
            }
        }
    };

    // ---- prologue ----
    load_idx(0, 0);
    load_idx(1, 1);
    load_idx(2, 2);
    bstage_ldg(0); bstage_sts(0);
    bstage_ldg(1); bstage_sts(1);
    table_ldg(0);
    table_ldg(1);
    cv_store(0);
    __syncthreads();

    // ---- fully-unrolled pipelined main loop ----
    #pragma unroll
    for (int c = 0; c < NCHUNK; ++c) {
        if (c + 3 < NCHUNK) load_idx(c + 3, (c + 3) % 3);
        if (c + 2 < NCHUNK) { table_ldg(c + 2); bstage_ldg(c + 2); }
        do_mma(c);
        if (c + 2 < NCHUNK) bstage_sts(c + 2);
        if (c + 1 < NCHUNK) cv_store(c + 1);
        __syncthreads();
    }

    // ---- epilogue: reduce k-halves, combine, MLP ----
    float* sFO = (float*)(smem + EXP_FO);
    float* sS  = (float*)(smem + EXP_S);
    float* sM  = (float*)(smem + EXP_M);
    float* sH  = (float*)(smem + EXP_H);

    const int r0 = slab * 16 + (l >> 2);
    const int r1 = r0 + 8;

    if (kh == 1) {
        #pragma unroll
        for (int t = 0; t < 4; ++t) {
            const int c0 = t * 8 + (l & 3) * 2;
            sFO[r0 * 33 + c0]     = acc[t][0];
            sFO[r0 * 33 + c0 + 1] = acc[t][1];
            sFO[r1 * 33 + c0]     = acc[t][2];
            sFO[r1 * 33 + c0 + 1] = acc[t][3];
            sS[r0 * 33 + c0]      = acc[t + 4][0];
            sS[r0 * 33 + c0 + 1]  = acc[t + 4][1];
            sS[r1 * 33 + c0]      = acc[t + 4][2];
            sS[r1 * 33 + c0 + 1]  = acc[t + 4][3];
        }
    }
    for (int i = tid; i < 1024; i += THREADS) {
        sM[i]        = lin1_w[i];
        sM[1056 + i] = lin2_w[i];
    }
    if (tid < 32) {
        sM[1024 + tid] = lin1_b[tid];
        sM[2080 + tid] = lin2_b[tid];
        sM[2112 + tid] = last_w[tid];
    }
    if (tid == 0) sM[2144] = last_b[0];
    __syncthreads();

    if (kh == 0) {
        #pragma unroll
        for (int t = 0; t < 4; ++t) {
            const int c0 = t * 8 + (l & 3) * 2;
            sFO[r0 * 33 + c0]     += acc[t][0];
            sFO[r0 * 33 + c0 + 1] += acc[t][1];
            sFO[r1 * 33 + c0]     += acc[t][2];
            sFO[r1 * 33 + c0 + 1] += acc[t][3];
            sS[r0 * 33 + c0]      += acc[t + 4][0];
            sS[r0 * 33 + c0 + 1]  += acc[t + 4][1];
            sS[r1 * 33 + c0]      += acc[t + 4][2];
            sS[r1 * 33 + c0 + 1]  += acc[t + 4][3];
        }
    }
    __syncthreads();

    // ---- MLP: 4 threads per row, 8 outputs each ----
    const int mrow = tid >> 2;
    const int mo   = tid & 3;

    float xr[32];
    #pragma unroll
    for (int j = 0; j < 32; ++j) {
        float s = sS[mrow * 33 + j];
        xr[j] = fmaf(s, s, sFO[mrow * 33 + j]);
    }
    #pragma unroll
    for (int i = 0; i < 8; ++i) {
        int oi = mo * 8 + i;
        float t = sM[1024 + oi];
        #pragma unroll
        for (int j4 = 0; j4 < 8; ++j4) {
            float4 w = *(const float4*)&sM[oi * 32 + j4 * 4];
            t = fmaf(xr[j4 * 4],     w.x, t);
            t = fmaf(xr[j4 * 4 + 1], w.y, t);
            t = fmaf(xr[j4 * 4 + 2], w.z, t);
            t = fmaf(xr[j4 * 4 + 3], w.w, t);
        }
        sH[mrow * 33 + oi] = fmaxf(t, 0.f);
    }
    __syncthreads();

    float hr[32];
    #pragma unroll
    for (int j = 0; j < 32; ++j) hr[j] = sH[mrow * 33 + j];
    #pragma unroll
    for (int i = 0; i < 8; ++i) {
        int oi = mo * 8 + i;
        float t = sM[2080 + oi];
        #pragma unroll
        for (int j4 = 0; j4 < 8; ++j4) {
            float4 w = *(const float4*)&sM[1056 + oi * 32 + j4 * 4];
            t = fmaf(hr[j4 * 4],     w.x, t);
            t = fmaf(hr[j4 * 4 + 1], w.y, t);
            t = fmaf(hr[j4 * 4 + 2], w.z, t);
            t = fmaf(hr[j4 * 4 + 3], w.w, t);
        }
        sFO[mrow * 33 + oi] = fmaxf(t, 0.f);   // reuse sFO for h2
    }
    __syncthreads();

    if (mo == 0) {
        float o = sM[2144];
        #pragma unroll
        for (int j = 0; j < 32; ++j) o = fmaf(sFO[mrow * 33 + j], sM[2112 + j], o);
        out[b0 + mrow] = o;
    }
}

extern "C" void kernel_launch(void* const* d_in, const int* in_sizes, int n_in,
                              void* d_out, int out_size) {
    const int*   Xi     = (const int*)  d_in[0];
    const float* Xv     = (const float*)d_in[1];
    const float* tables = (const float*)d_in[2];
    const float* W1     = (const float*)d_in[3];
    const float* Wi     = (const float*)d_in[4];
    const float* lin1_w = (const float*)d_in[5];
    const float* lin1_b = (const float*)d_in[6];
    const float* lin2_w = (const float*)d_in[7];
    const float* lin2_b = (const float*)d_in[8];
    const float* last_w = (const float*)d_in[9];
    const float* last_b = (const float*)d_in[10];
    float* out = (float*)d_out;

    static bool attr_set = false;
    if (!attr_set) {
        cudaFuncSetAttribute(pnn_kernel, cudaFuncAttributeMaxDynamicSharedMemorySize, SMEM_BYTES);
        attr_set = true;
    }

    prep_kernel<<<(2 * 40 * 4 * 32 * 4 + 255) / 256, 256>>>(W1, Wi);
    pnn_kernel<<<BATCH / ROWSPB, THREADS, SMEM_BYTES>>>(
        Xi, Xv, tables, lin1_w, lin1_b, lin2_w, lin2_b, last_w, last_b, out);
}

// round 9
// speedup vs baseline: 1.2012x; 1.2012x over previous
#include <cuda_runtime.h>
#include <cuda_bf16.h>
#include <cstdint>

#define NFIELD 39
#define VOCAB  200000
#define BATCH  16384
#define ROWSPB 64
#define THREADS 256
#define NCHUNK 10          // 10 chunks x 4 fields (kstep16) = 640 padded k

// B fragments, chunk-major for streaming:
// [chunk10][hl2][ks4][tp4][lane32][4 u32] = 160KB; one chunk = 16KB contiguous
__device__ __align__(16) uint32_t BfragG[10 * 2 * 4 * 4 * 32 * 4];

__global__ void prep_kernel(const float* __restrict__ W1, const float* __restrict__ Wi) {
    int i = blockIdx.x * blockDim.x + threadIdx.x;
    if (i >= 10 * 2 * 4 * 4 * 32 * 4) return;
    int reg = i & 3;
    int l   = (i >> 2) & 31;
    int tp  = (i >> 7) & 3;
    int s   = (i >> 9) & 3;
    int hl  = (i >> 11) & 1;
    int c   = i >> 12;
    int gs = c * 4 + s;
    int t  = tp * 2 + (reg >> 1);
    int n  = t * 8 + (l >> 2);
    int k0 = gs * 16 + (l & 3) * 2 + (reg & 1) * 8;
    float v0 = 0.f, v1 = 0.f;
    if (k0 < 624)     v0 = (n < 32) ? W1[n * 624 + k0]     : Wi[(n - 32) * 624 + k0];
    if (k0 + 1 < 624) v1 = (n < 32) ? W1[n * 624 + k0 + 1] : Wi[(n - 32) * 624 + k0 + 1];
    float h0 = __bfloat162float(__float2bfloat16(v0));
    float h1 = __bfloat162float(__float2bfloat16(v1));
    uint32_t w;
    if (hl == 0) {
        asm("cvt.rn.bf16x2.f32 %0, %1, %2;" : "=r"(w) : "f"(h1), "f"(h0));
    } else {
        float r0 = v0 - h0, r1 = v1 - h1;
        asm("cvt.rn.bf16x2.f32 %0, %1, %2;" : "=r"(w) : "f"(r1), "f"(r0));
    }
    BfragG[i] = w;
}

__device__ __forceinline__ uint32_t packbf(float lo_elem, float hi_elem) {
    uint32_t r;
    asm("cvt.rn.bf16x2.f32 %0, %1, %2;" : "=r"(r) : "f"(hi_elem), "f"(lo_elem));
    return r;
}
__device__ __forceinline__ void mma16816(float* d, uint32_t a0, uint32_t a1, uint32_t a2, uint32_t a3,
                                         uint32_t b0, uint32_t b1) {
    asm volatile("mma.sync.aligned.m16n8k16.row.col.f32.bf16.bf16.f32 "
                 "{%0,%1,%2,%3}, {%4,%5,%6,%7}, {%8,%9}, {%0,%1,%2,%3};"
                 : "+f"(d[0]), "+f"(d[1]), "+f"(d[2]), "+f"(d[3])
                 : "r"(a0), "r"(a1), "r"(a2), "r"(a3), "r"(b0), "r"(b1));
}
__device__ __forceinline__ void ldsm4(uint32_t& r0, uint32_t& r1, uint32_t& r2, uint32_t& r3,
                                      uint32_t addr) {
    asm volatile("ldmatrix.sync.aligned.m8n8.x4.shared.b16 {%0,%1,%2,%3}, [%4];"
                 : "=r"(r0), "=r"(r1), "=r"(r2), "=r"(r3) : "r"(addr));
}

// smem layout (bytes):
//   A: 2 bufs x [hl2][slab4][ks4][512B] = 2 x 16384 @ 0
//   B: 3 bufs x 16384 (one chunk each)  @ 32768
//   sM: MLP weights (2145 floats)       @ 81920
#define OFF_A 0
#define ABUF  16384
#define OFF_B 32768
#define BBUF  16384
#define OFF_M 81920
#define SMEM_BYTES (81920 + 2145 * 4)
// epilogue aliases inside the A region (32KB):
#define EXP_FO 0        // 64 x 33 floats
#define EXP_S  8448     // 64 x 33 floats
#define EXP_H  16896    // 64 x 33 floats

__global__ __launch_bounds__(THREADS, 2)
void pnn_kernel(const int*   __restrict__ Xi,
                const float* __restrict__ Xv,
                const float* __restrict__ tables,
                const float* __restrict__ lin1_w,
                const float* __restrict__ lin1_b,
                const float* __restrict__ lin2_w,
                const float* __restrict__ lin2_b,
                const float* __restrict__ last_w,
                const float* __restrict__ last_b,
                float*       __restrict__ out) {
    extern __shared__ unsigned char smem[];
    const uint32_t sbase = (uint32_t)__cvta_generic_to_shared(smem);

    const int tid = threadIdx.x;
    const int wid = tid >> 5;
    const int l   = tid & 31;
    const int b0  = blockIdx.x * ROWSPB;

    // MMA mapping: warp = (slab, n-half). Full K per warp -> private acc, no reduction.
    const int slab = wid >> 1;       // rows [slab*16, slab*16+16), slab 0..3
    const int nh   = wid & 1;        // B tp pairs {2nh, 2nh+1} -> ntiles [nh*4, nh*4+4)

    // gather mapping: quad per row: 4 threads x 16B segments; 4 fields per thread per chunk
    const int qrow = tid >> 2;       // 0..63
    const int q    = tid & 3;        // 16B segment of 64B embedding row

    int    nidx[3][4];
    float  nxv[3][4];
    float4 tdat[2][4];
    uint4  tbb[4];

    float acc[4][4];                 // 4 local ntiles x 4 regs
    #pragma unroll
    for (int t = 0; t < 4; ++t)
        #pragma unroll
        for (int r = 0; r < 4; ++r) acc[t][r] = 0.f;

    const uint4* srcB = (const uint4*)BfragG;
    uint4* dstB = (uint4*)(smem + OFF_B);

    auto load_idx = [&](int c, int slot) {
        #pragma unroll
        for (int j = 0; j < 4; ++j) {
            int f = c * 4 + j;
            if (f < NFIELD) {
                nidx[slot][j] = Xi[(size_t)(b0 + qrow) * NFIELD + f];
                nxv[slot][j]  = Xv[(size_t)(b0 + qrow) * NFIELD + f];
            } else {
                nidx[slot][j] = 0;
                nxv[slot][j]  = 0.f;
            }
        }
    };
    auto table_ldg = [&](int c) {
        const int islot = c % 3, tslot = c & 1;
        #pragma unroll
        for (int j = 0; j < 4; ++j) {
            int f = c * 4 + j;
            if (f < NFIELD)
                tdat[tslot][j] = *(((const float4*)tables) + ((long)f * VOCAB + nidx[islot][j]) * 4 + q);
            else
                tdat[tslot][j] = make_float4(0.f, 0.f, 0.f, 0.f);
        }
    };
    auto cv_store = [&](int c) {
        const int islot = c % 3, tslot = c & 1;
        const int sl = qrow >> 4;
        const int inoff = (q >> 1) * 256 + (qrow & 15) * 16 + (q & 1) * 8;
        #pragma unroll
        for (int j = 0; j < 4; ++j) {
            float xv = nxv[islot][j];
            float4 t4 = tdat[tslot][j];
            float v0 = t4.x * xv, v1 = t4.y * xv, v2 = t4.z * xv, v3 = t4.w * xv;
            float r0 = v0 - __bfloat162float(__float2bfloat16(v0));
            float r1 = v1 - __bfloat162float(__float2bfloat16(v1));
            float r2 = v2 - __bfloat162float(__float2bfloat16(v2));
            float r3 = v3 - __bfloat162float(__float2bfloat16(v3));
            unsigned char* bh = smem + (c & 1) * ABUF + ((0 * 4 + sl) * 4 + j) * 512 + inoff;
            unsigned char* bl = smem + (c & 1) * ABUF + ((1 * 4 + sl) * 4 + j) * 512 + inoff;
            *(uint2*)bh = make_uint2(packbf(v0, v1), packbf(v2, v3));
            *(uint2*)bl = make_uint2(packbf(r0, r1), packbf(r2, r3));
        }
    };
    auto bstage_ldg = [&](int c) {
        #pragma unroll
        for (int i = 0; i < 4; ++i) tbb[i] = srcB[c * 1024 + i * 256 + tid];
    };
    auto bstage_sts = [&](int c) {
        #pragma unroll
        for (int i = 0; i < 4; ++i) dstB[(c % 3) * 1024 + i * 256 + tid] = tbb[i];
    };
    auto do_mma = [&](int c) {
        const uint32_t bbase = (uint32_t)(OFF_B + (c % 3) * BBUF);
        const uint32_t abase = (uint32_t)((c & 1) * ABUF);
        const uint32_t laddr = (uint32_t)((l & 15) * 16 + (l >> 4) * 256);
        #pragma unroll
        for (int s = 0; s < 4; ++s) {
            uint32_t ah0, ah1, ah2, ah3, al0, al1, al2, al3;
            ldsm4(ah0, ah1, ah2, ah3, sbase + abase + ((0 * 4 + slab) * 4 + s) * 512 + laddr);
            ldsm4(al0, al1, al2, al3, sbase + abase + ((1 * 4 + slab) * 4 + s) * 512 + laddr);
            #pragma unroll
            for (int tpl = 0; tpl < 2; ++tpl) {
                const int tp = nh * 2 + tpl;
                uint4 Bh = *(const uint4*)(smem + bbase + ((0 * 4 + s) * 4 + tp) * 512 + l * 16);
                uint4 Bl = *(const uint4*)(smem + bbase + ((1 * 4 + s) * 4 + tp) * 512 + l * 16);
                mma16816(acc[2 * tpl],     ah0, ah1, ah2, ah3, Bh.x, Bh.y);
                mma16816(acc[2 * tpl + 1], ah0, ah1, ah2, ah3, Bh.z, Bh.w);
                mma16816(acc[2 * tpl],     ah0, ah1, ah2, ah3, Bl.x, Bl.y);
                mma16816(acc[2 * tpl + 1], ah0, ah1, ah2, ah3, Bl.z, Bl.w);
                mma16816(acc[2 * tpl],     al0, al1, al2, al3, Bh.x, Bh.y);
                mma16816(acc[2 * tpl + 1], al0, al1, al2, al3, Bh.z, Bh.w);
            }
        }
    };

    // ---- prologue ----
    load_idx(0, 0);
    load_idx(1, 1);
    load_idx(2, 2);
    bstage_ldg(0); bstage_sts(0);
    bstage_ldg(1); bstage_sts(1);
    table_ldg(0);
    table_ldg(1);
    cv_store(0);
    __syncthreads();

    // ---- pipelined main loop (A double-buffered, B triple-buffered) ----
    #pragma unroll
    for (int c = 0; c < NCHUNK; ++c) {
        if (c + 3 < NCHUNK) load_idx(c + 3, (c + 3) % 3);
        if (c + 2 < NCHUNK) { table_ldg(c + 2); bstage_ldg(c + 2); }
        do_mma(c);
        if (c + 2 < NCHUNK) bstage_sts(c + 2);    // buf (c+2)%3: not read until after next barrier
        if (c + 1 < NCHUNK) cv_store(c + 1);
        __syncthreads();
    }

    // ---- epilogue: single writer per (row, col) ----
    float* sFO = (float*)(smem + EXP_FO);
    float* sS  = (float*)(smem + EXP_S);
    float* sH  = (float*)(smem + EXP_H);
    float* sM  = (float*)(smem + OFF_M);

    {
        const int r0 = slab * 16 + (l >> 2);
        const int r1 = r0 + 8;
        float* dst = nh ? sS : sFO;
        #pragma unroll
        for (int t = 0; t < 4; ++t) {
            const int c0 = t * 8 + (l & 3) * 2;   // ntile local t -> cols [t*8 .. ) within half
            dst[r0 * 33 + c0]     = acc[t][0];
            dst[r0 * 33 + c0 + 1] = acc[t][1];
            dst[r1 * 33 + c0]     = acc[t][2];
            dst[r1 * 33 + c0 + 1] = acc[t][3];
        }
    }
    for (int i = tid; i < 1024; i += THREADS) {
        sM[i]        = lin1_w[i];
        sM[1056 + i] = lin2_w[i];
    }
    if (tid < 32) {
        sM[1024 + tid] = lin1_b[tid];
        sM[2080 + tid] = lin2_b[tid];
        sM[2112 + tid] = last_w[tid];
    }
    if (tid == 0) sM[2144] = last_b[0];
    __syncthreads();

    // ---- MLP: 4 threads per row, 8 outputs each ----
    const int mrow = tid >> 2;
    const int mo   = tid & 3;

    float xr[32];
    #pragma unroll
    for (int j = 0; j < 32; ++j) {
        float s = sS[mrow * 33 + j];
        xr[j] = fmaf(s, s, sFO[mrow * 33 + j]);
    }
    #pragma unroll
    for (int i = 0; i < 8; ++i) {
        int oi = mo * 8 + i;
        float t = sM[1024 + oi];
        #pragma unroll
        for (int j4 = 0; j4 < 8; ++j4) {
            float4 w = *(const float4*)&sM[oi * 32 + j4 * 4];
            t = fmaf(xr[j4 * 4],     w.x, t);
            t = fmaf(xr[j4 * 4 + 1], w.y, t);
            t = fmaf(xr[j4 * 4 + 2], w.z, t);
            t = fmaf(xr[j4 * 4 + 3], w.w, t);
        }
        sH[mrow * 33 + oi] = fmaxf(t, 0.f);
    }
    __syncthreads();

    float hr[32];
    #pragma unroll
    for (int j = 0; j < 32; ++j) hr[j] = sH[mrow * 33 + j];
    #pragma unroll
    for (int i = 0; i < 8; ++i) {
        int oi = mo * 8 + i;
        float t = sM[2080 + oi];
        #pragma unroll
        for (int j4 = 0; j4 < 8; ++j4) {
            float4 w = *(const float4*)&sM[1056 + oi * 32 + j4 * 4];
            t = fmaf(hr[j4 * 4],     w.x, t);
            t = fmaf(hr[j4 * 4 + 1], w.y, t);
            t = fmaf(hr[j4 * 4 + 2], w.z, t);
            t = fmaf(hr[j4 * 4 + 3], w.w, t);
        }
        sFO[mrow * 33 + oi] = fmaxf(t, 0.f);   // reuse sFO for h2
    }
    __syncthreads();

    if (mo == 0) {
        float o = sM[2144];
        #pragma unroll
        for (int j = 0; j < 32; ++j) o = fmaf(sFO[mrow * 33 + j], sM[2112 + j], o);
        out[b0 + mrow] = o;
    }
}

extern "C" void kernel_launch(void* const* d_in, const int* in_sizes, int n_in,
                              void* d_out, int out_size) {
    const int*   Xi     = (const int*)  d_in[0];
    const float* Xv     = (const float*)d_in[1];
    const float* tables = (const float*)d_in[2];
    const float* W1     = (const float*)d_in[3];
    const float* Wi     = (const float*)d_in[4];
    const float* lin1_w = (const float*)d_in[5];
    const float* lin1_b = (const float*)d_in[6];
    const float* lin2_w = (const float*)d_in[7];
    const float* lin2_b = (const float*)d_in[8];
    const float* last_w = (const float*)d_in[9];
    const float* last_b = (const float*)d_in[10];
    float* out = (float*)d_out;

    static bool attr_set = false;
    if (!attr_set) {
        cudaFuncSetAttribute(pnn_kernel, cudaFuncAttributeMaxDynamicSharedMemorySize, SMEM_BYTES);
        attr_set = true;
    }

    prep_kernel<<<(10 * 2 * 4 * 4 * 32 * 4 + 255) / 256, 256>>>(W1, Wi);
    pnn_kernel<<<BATCH / ROWSPB, THREADS, SMEM_BYTES>>>(
        Xi, Xv, tables, lin1_w, lin1_b, lin2_w, lin2_b, last_w, last_b, out);
}

// round 10
// speedup vs baseline: 1.9901x; 1.6568x over previous
#include <cuda_runtime.h>
#include <cuda_bf16.h>
#include <cstdint>

#define NFIELD 39
#define VOCAB  200000
#define BATCH  16384
#define ROWSPB 128
#define THREADS 256
#define NCHUNK 10          // 10 chunks x 4 fields (kstep16) = 640 padded k

// B fragments, chunk-major: [chunk10][hl2][s4][tp4][lane32][4 u32] = 160KB
// (identical layout/indexing to validated R9 prep)
__device__ __align__(16) uint32_t BfragG[10 * 2 * 4 * 4 * 32 * 4];

__global__ void prep_kernel(const float* __restrict__ W1, const float* __restrict__ Wi) {
    int i = blockIdx.x * blockDim.x + threadIdx.x;
    if (i >= 10 * 2 * 4 * 4 * 32 * 4) return;
    int reg = i & 3;
    int l   = (i >> 2) & 31;
    int tp  = (i >> 7) & 3;
    int s   = (i >> 9) & 3;
    int hl  = (i >> 11) & 1;
    int c   = i >> 12;
    int gs = c * 4 + s;
    int t  = tp * 2 + (reg >> 1);
    int n  = t * 8 + (l >> 2);
    int k0 = gs * 16 + (l & 3) * 2 + (reg & 1) * 8;
    float v0 = 0.f, v1 = 0.f;
    if (k0 < 624)     v0 = (n < 32) ? W1[n * 624 + k0]     : Wi[(n - 32) * 624 + k0];
    if (k0 + 1 < 624) v1 = (n < 32) ? W1[n * 624 + k0 + 1] : Wi[(n - 32) * 624 + k0 + 1];
    float h0 = __bfloat162float(__float2bfloat16(v0));
    float h1 = __bfloat162float(__float2bfloat16(v1));
    uint32_t w;
    if (hl == 0) {
        asm("cvt.rn.bf16x2.f32 %0, %1, %2;" : "=r"(w) : "f"(h1), "f"(h0));
    } else {
        float r0 = v0 - h0, r1 = v1 - h1;
        asm("cvt.rn.bf16x2.f32 %0, %1, %2;" : "=r"(w) : "f"(r1), "f"(r0));
    }
    BfragG[i] = w;
}

__device__ __forceinline__ uint32_t packbf(float lo_elem, float hi_elem) {
    uint32_t r;
    asm("cvt.rn.bf16x2.f32 %0, %1, %2;" : "=r"(r) : "f"(hi_elem), "f"(lo_elem));
    return r;
}
__device__ __forceinline__ void mma16816(float* d, uint32_t a0, uint32_t a1, uint32_t a2, uint32_t a3,
                                         uint32_t b0, uint32_t b1) {
    asm volatile("mma.sync.aligned.m16n8k16.row.col.f32.bf16.bf16.f32 "
                 "{%0,%1,%2,%3}, {%4,%5,%6,%7}, {%8,%9}, {%0,%1,%2,%3};"
                 : "+f"(d[0]), "+f"(d[1]), "+f"(d[2]), "+f"(d[3])
                 : "r"(a0), "r"(a1), "r"(a2), "r"(a3), "r"(b0), "r"(b1));
}
__device__ __forceinline__ void ldsm4(uint32_t& r0, uint32_t& r1, uint32_t& r2, uint32_t& r3,
                                      uint32_t addr) {
    asm volatile("ldmatrix.sync.aligned.m8n8.x4.shared.b16 {%0,%1,%2,%3}, [%4];"
                 : "=r"(r0), "=r"(r1), "=r"(r2), "=r"(r3) : "r"(addr));
}
__device__ __forceinline__ void pair_bar(int id) {
    asm volatile("bar.sync %0, %1;" :: "r"(id), "r"(64) : "memory");
}

// smem (64KB): A only: [pair4][buf2][hl2][s4][m2 x 512B]  (pair stride 16KB, buf 8KB)
#define SMEM_BYTES 65536
// epilogue aliases (all warps done with A by then):
#define EXP_FO 0        // 128 x 33 floats
#define EXP_S  16896
#define EXP_M  33792    // MLP weights (2145 floats)
#define EXP_H  42384

__global__ __launch_bounds__(THREADS, 1)
void pnn_kernel(const int*   __restrict__ Xi,
                const float* __restrict__ Xv,
                const float* __restrict__ tables,
                const float* __restrict__ lin1_w,
                const float* __restrict__ lin1_b,
                const float* __restrict__ lin2_w,
                const float* __restrict__ lin2_b,
                const float* __restrict__ last_w,
                const float* __restrict__ last_b,
                float*       __restrict__ out) {
    extern __shared__ unsigned char smem[];
    const uint32_t sbase = (uint32_t)__cvta_generic_to_shared(smem);

    const int tid = threadIdx.x;
    const int wid = tid >> 5;
    const int l   = tid & 31;
    const int b0  = blockIdx.x * ROWSPB;

    // MMA mapping: pair p owns rows [p*32, p*32+32); nh selects cols [nh*32, +32)
    const int p  = wid >> 1;
    const int nh = wid & 1;
    const uint32_t apair = (uint32_t)(p * 16384);

    // gather mapping (pair-private): 64 threads; quad = (row_local, field) item
    const int pt = tid & 63;
    const int qi = pt >> 2;          // 0..15
    const int q  = pt & 3;           // 16B segment of 64B embedding row

    int    nidx[3][8];
    float  nxv[3][8];
    float4 tdat[2][8];

    float acc[2][4][4];              // [m][local ntile][reg]
    #pragma unroll
    for (int m = 0; m < 2; ++m)
        #pragma unroll
        for (int t = 0; t < 4; ++t)
            #pragma unroll
            for (int r = 0; r < 4; ++r) acc[m][t][r] = 0.f;

    const uint4* __restrict__ Bp = (const uint4*)BfragG;

    auto load_idx = [&](int c, int slot) {
        #pragma unroll
        for (int it = 0; it < 8; ++it) {
            int rl = (it >> 2) * 16 + qi;
            int f  = c * 4 + (it & 3);
            int row = b0 + p * 32 + rl;
            if (f < NFIELD) {
                nidx[slot][it] = Xi[(size_t)row * NFIELD + f];
                nxv[slot][it]  = Xv[(size_t)row * NFIELD + f];
            } else {
                nidx[slot][it] = 0;
                nxv[slot][it]  = 0.f;
            }
        }
    };
    auto table_ldg = [&](int c) {
        const int islot = c % 3, tslot = c & 1;
        #pragma unroll
        for (int it = 0; it < 8; ++it) {
            int f = c * 4 + (it & 3);
            if (f < NFIELD)
                tdat[tslot][it] = *(((const float4*)tables) + ((long)f * VOCAB + nidx[islot][it]) * 4 + q);
            else
                tdat[tslot][it] = make_float4(0.f, 0.f, 0.f, 0.f);
        }
    };
    auto cv_store = [&](int c) {
        const int islot = c % 3, tslot = c & 1;
        const uint32_t bufo = apair + (uint32_t)((c & 1) * 8192);
        #pragma unroll
        for (int it = 0; it < 8; ++it) {
            int rl = (it >> 2) * 16 + qi;
            int j  = it & 3;
            float xv = nxv[islot][it];
            float4 t4 = tdat[tslot][it];
            float v0 = t4.x * xv, v1 = t4.y * xv, v2 = t4.z * xv, v3 = t4.w * xv;
            float r0 = v0 - __bfloat162float(__float2bfloat16(v0));
            float r1 = v1 - __bfloat162float(__float2bfloat16(v1));
            float r2 = v2 - __bfloat162float(__float2bfloat16(v2));
            float r3 = v3 - __bfloat162float(__float2bfloat16(v3));
            uint32_t inoff = (uint32_t)((rl >> 4) * 512 + (q >> 1) * 256 + (rl & 15) * 16 + (q & 1) * 8);
            unsigned char* bh = smem + bufo + (0 * 4 + j) * 1024 + inoff;
            unsigned char* bl = smem + bufo + (4 + j) * 1024 + inoff;
            *(uint2*)bh = make_uint2(packbf(v0, v1), packbf(v2, v3));
            *(uint2*)bl = make_uint2(packbf(r0, r1), packbf(r2, r3));
        }
    };
    auto do_mma = [&](int c) {
        const uint32_t abase = sbase + apair + (uint32_t)((c & 1) * 8192);
        const uint32_t laddr = (uint32_t)((l & 15) * 16 + (l >> 4) * 256);
        #pragma unroll
        for (int s = 0; s < 4; ++s) {
            // B frags straight from global (L1-resident after first touch)
            uint4 Bh0 = Bp[c * 1024 + 0 * 512 + s * 128 + (nh * 2 + 0) * 32 + l];
            uint4 Bh1 = Bp[c * 1024 + 0 * 512 + s * 128 + (nh * 2 + 1) * 32 + l];
            uint4 Bl0 = Bp[c * 1024 + 1 * 512 + s * 128 + (nh * 2 + 0) * 32 + l];
            uint4 Bl1 = Bp[c * 1024 + 1 * 512 + s * 128 + (nh * 2 + 1) * 32 + l];
            #pragma unroll
            for (int m = 0; m < 2; ++m) {
                uint32_t ah0, ah1, ah2, ah3, al0, al1, al2, al3;
                ldsm4(ah0, ah1, ah2, ah3, abase + (0 * 4 + s) * 1024 + m * 512 + laddr);
                ldsm4(al0, al1, al2, al3, abase + (4 + s) * 1024 + m * 512 + laddr);
                mma16816(acc[m][0], ah0, ah1, ah2, ah3, Bh0.x, Bh0.y);
                mma16816(acc[m][1], ah0, ah1, ah2, ah3, Bh0.z, Bh0.w);
                mma16816(acc[m][2], ah0, ah1, ah2, ah3, Bh1.x, Bh1.y);
                mma16816(acc[m][3], ah0, ah1, ah2, ah3, Bh1.z, Bh1.w);
                mma16816(acc[m][0], ah0, ah1, ah2, ah3, Bl0.x, Bl0.y);
                mma16816(acc[m][1], ah0, ah1, ah2, ah3, Bl0.z, Bl0.w);
                mma16816(acc[m][2], ah0, ah1, ah2, ah3, Bl1.x, Bl1.y);
                mma16816(acc[m][3], ah0, ah1, ah2, ah3, Bl1.z, Bl1.w);
                mma16816(acc[m][0], al0, al1, al2, al3, Bh0.x, Bh0.y);
                mma16816(acc[m][1], al0, al1, al2, al3, Bh0.z, Bh0.w);
                mma16816(acc[m][2], al0, al1, al2, al3, Bh1.x, Bh1.y);
                mma16816(acc[m][3], al0, al1, al2, al3, Bh1.z, Bh1.w);
            }
        }
    };

    // ---- prologue ----
    load_idx(0, 0);
    load_idx(1, 1);
    load_idx(2, 2);
    table_ldg(0);
    table_ldg(1);
    cv_store(0);
    pair_bar(p + 1);

    // ---- free-running pipelined loop (pair-local sync only) ----
    #pragma unroll
    for (int c = 0; c < NCHUNK; ++c) {
        if (c + 3 < NCHUNK) load_idx(c + 3, (c + 3) % 3);
        if (c + 2 < NCHUNK) table_ldg(c + 2);
        do_mma(c);
        if (c + 1 < NCHUNK) cv_store(c + 1);
        if (c + 1 < NCHUNK) pair_bar(p + 1);
    }
    __syncthreads();

    // ---- epilogue (aliases A region) ----
    float* sFO = (float*)(smem + EXP_FO);
    float* sS  = (float*)(smem + EXP_S);
    float* sM  = (float*)(smem + EXP_M);
    float* sH  = (float*)(smem + EXP_H);

    {
        float* dst = nh ? sS : sFO;
        #pragma unroll
        for (int m = 0; m < 2; ++m) {
            const int r0 = p * 32 + m * 16 + (l >> 2);
            const int r1 = r0 + 8;
            #pragma unroll
            for (int t = 0; t < 4; ++t) {
                const int c0 = t * 8 + (l & 3) * 2;
                dst[r0 * 33 + c0]     = acc[m][t][0];
                dst[r0 * 33 + c0 + 1] = acc[m][t][1];
                dst[r1 * 33 + c0]     = acc[m][t][2];
                dst[r1 * 33 + c0 + 1] = acc[m][t][3];
            }
        }
    }
    for (int i = tid; i < 1024; i += THREADS) {
        sM[i]        = lin1_w[i];
        sM[1056 + i] = lin2_w[i];
    }
    if (tid < 32) {
        sM[1024 + tid] = lin1_b[tid];
        sM[2080 + tid] = lin2_b[tid];
        sM[2112 + tid] = last_w[tid];
    }
    if (tid == 0) sM[2144] = last_b[0];
    __syncthreads();

    // ---- MLP: 2 threads per row, 16 outputs each ----
    const int mrow = tid >> 1;
    const int mh   = tid & 1;

    float xr[32];
    #pragma unroll
    for (int j = 0; j < 32; ++j) {
        float s = sS[mrow * 33 + j];
        xr[j] = fmaf(s, s, sFO[mrow * 33 + j]);
    }
    #pragma unroll
    for (int i = 0; i < 16; ++i) {
        int oi = mh * 16 + i;
        float t = sM[1024 + oi];
        #pragma unroll
        for (int j4 = 0; j4 < 8; ++j4) {
            float4 w = *(const float4*)&sM[oi * 32 + j4 * 4];
            t = fmaf(xr[j4 * 4],     w.x, t);
            t = fmaf(xr[j4 * 4 + 1], w.y, t);
            t = fmaf(xr[j4 * 4 + 2], w.z, t);
            t = fmaf(xr[j4 * 4 + 3], w.w, t);
        }
        sH[mrow * 33 + oi] = fmaxf(t, 0.f);
    }
    __syncthreads();

    float hr[32];
    #pragma unroll
    for (int j = 0; j < 32; ++j) hr[j] = sH[mrow * 33 + j];
    #pragma unroll
    for (int i = 0; i < 16; ++i) {
        int oi = mh * 16 + i;
        float t = sM[2080 + oi];
        #pragma unroll
        for (int j4 = 0; j4 < 8; ++j4) {
            float4 w = *(const float4*)&sM[1056 + oi * 32 + j4 * 4];
            t = fmaf(hr[j4 * 4],     w.x, t);
            t = fmaf(hr[j4 * 4 + 1], w.y, t);
            t = fmaf(hr[j4 * 4 + 2], w.z, t);
            t = fmaf(hr[j4 * 4 + 3], w.w, t);
        }
        sFO[mrow * 33 + oi] = fmaxf(t, 0.f);   // reuse sFO for h2
    }
    __syncthreads();

    if (mh == 0) {
        float o = sM[2144];
        #pragma unroll
        for (int j = 0; j < 32; ++j) o = fmaf(sFO[mrow * 33 + j], sM[2112 + j], o);
        out[b0 + mrow] = o;
    }
}

extern "C" void kernel_launch(void* const* d_in, const int* in_sizes, int n_in,
                              void* d_out, int out_size) {
    const int*   Xi     = (const int*)  d_in[0];
    const float* Xv     = (const float*)d_in[1];
    const float* tables = (const float*)d_in[2];
    const float* W1     = (const float*)d_in[3];
    const float* Wi     = (const float*)d_in[4];
    const float* lin1_w = (const float*)d_in[5];
    const float* lin1_b = (const float*)d_in[6];
    const float* lin2_w = (const float*)d_in[7];
    const float* lin2_b = (const float*)d_in[8];
    const float* last_w = (const float*)d_in[9];
    const float* last_b = (const float*)d_in[10];
    float* out = (float*)d_out;

    static bool attr_set = false;
    if (!attr_set) {
        cudaFuncSetAttribute(pnn_kernel, cudaFuncAttributeMaxDynamicSharedMemorySize, SMEM_BYTES);
        attr_set = true;
    }

    prep_kernel<<<(10 * 2 * 4 * 4 * 32 * 4 + 255) / 256, 256>>>(W1, Wi);
    pnn_kernel<<<BATCH / ROWSPB, THREADS, SMEM_BYTES>>>(
        Xi, Xv, tables, lin1_w, lin1_b, lin2_w, lin2_b, last_w, last_b, out);
}